// round 1
// baseline (speedup 1.0000x reference)
#include <cuda_runtime.h>
#include <math.h>

#define DIM    1024
#define NH     16
#define HD     64
#define BATCH  4
#define SEQ    2048
#define MTOT   (BATCH*SEQ)   // 8192

// ---------------------------------------------------------------------------
// Scratch (static __device__ arrays: allocation-free per harness rules)
// ---------------------------------------------------------------------------
__device__ float g_q[(size_t)BATCH*NH*SEQ*HD];   // [b,h,s,d]
__device__ float g_k[(size_t)BATCH*NH*SEQ*HD];
__device__ float g_v[(size_t)BATCH*NH*SEQ*HD];
__device__ float g_attn[(size_t)MTOT*DIM];       // [b,s,h*d]

// ---------------------------------------------------------------------------
// SGEMM: C[M,N] = A[M,K] @ B[K,N], all row-major, fp32.
// 128x128 block tile, k-tile 8, 256 threads, 8x8 register microtile.
// MODE 0: plain C[m*N+n].
// MODE 1: head-split epilogue -> C[((b*NH+h)*SEQ+s)*HD + d], b=m/SEQ, s=m%SEQ,
//         h=n/HD, d=n%HD.
// ---------------------------------------------------------------------------
template<int MODE>
__global__ __launch_bounds__(256)
void gemm_kernel(const float* __restrict__ A, const float* __restrict__ B,
                 float* __restrict__ C, int M, int N, int K)
{
    __shared__ float As[8][128];
    __shared__ float Bs[8][128];

    const int tid = threadIdx.x;
    const int bm  = blockIdx.y;
    const int bn  = blockIdx.x;
    const int tx  = tid & 15;     // 0..15  (cols tx*8..tx*8+7)
    const int ty  = tid >> 4;     // 0..15  (rows ty*8..ty*8+7)

    float c[8][8];
    #pragma unroll
    for (int i = 0; i < 8; i++)
        #pragma unroll
        for (int j = 0; j < 8; j++) c[i][j] = 0.f;

    // A-tile loader: each thread loads one float4. row = tid/2, k-quad = (tid&1)*4
    const int arow = tid >> 1;
    const int akq  = (tid & 1) * 4;
    // B-tile loader: krow = tid/32, n0 = (tid&31)*4
    const int bkrow = tid >> 5;
    const int bn0   = (tid & 31) * 4;

    const float* Aptr = A + (size_t)(bm*128 + arow) * K + akq;
    const float* Bptr = B + (size_t)bkrow * N + bn*128 + bn0;

    for (int kt = 0; kt < K; kt += 8) {
        float4 av = *(const float4*)(Aptr + kt);
        As[akq+0][arow] = av.x;
        As[akq+1][arow] = av.y;
        As[akq+2][arow] = av.z;
        As[akq+3][arow] = av.w;
        float4 bv = *(const float4*)(Bptr + (size_t)kt * N);
        *(float4*)&Bs[bkrow][bn0] = bv;
        __syncthreads();

        #pragma unroll
        for (int kk = 0; kk < 8; kk++) {
            float ar[8], br[8];
            *(float4*)&ar[0] = *(const float4*)&As[kk][ty*8];
            *(float4*)&ar[4] = *(const float4*)&As[kk][ty*8+4];
            *(float4*)&br[0] = *(const float4*)&Bs[kk][tx*8];
            *(float4*)&br[4] = *(const float4*)&Bs[kk][tx*8+4];
            #pragma unroll
            for (int i = 0; i < 8; i++)
                #pragma unroll
                for (int j = 0; j < 8; j++)
                    c[i][j] += ar[i] * br[j];
        }
        __syncthreads();
    }

    // epilogue
    const int n0 = bn*128 + tx*8;   // 8 contiguous columns, always within one head (8 | 64)
    #pragma unroll
    for (int i = 0; i < 8; i++) {
        const int m = bm*128 + ty*8 + i;
        if (MODE == 0) {
            float4 v0 = make_float4(c[i][0], c[i][1], c[i][2], c[i][3]);
            float4 v1 = make_float4(c[i][4], c[i][5], c[i][6], c[i][7]);
            *(float4*)&C[(size_t)m*N + n0]     = v0;
            *(float4*)&C[(size_t)m*N + n0 + 4] = v1;
        } else {
            const int b = m >> 11, s = m & (SEQ-1);
            const int h = n0 >> 6, d0 = n0 & 63;
            const size_t base = (((size_t)b*NH + h)*SEQ + s)*HD + d0;
            float4 v0 = make_float4(c[i][0], c[i][1], c[i][2], c[i][3]);
            float4 v1 = make_float4(c[i][4], c[i][5], c[i][6], c[i][7]);
            *(float4*)&C[base]     = v0;
            *(float4*)&C[base + 4] = v1;
        }
    }
}

// ---------------------------------------------------------------------------
// Causal flash attention, fp32. Br=Bc=64, D=64.
// Grid: (SEQ/64, BATCH*NH). 128 threads.
// Thread (tr,tc): tr=tid/8 -> rows tr*4..+3, tc=tid%8 -> cols tc*8..+7.
// smem: sQ[64][65], sK[64][65] (aliased as sP), sV[64][64] -> 49664 B dynamic.
// Output layout: [b, s, h*HD + d] so the final GEMM is plain row-major.
// ---------------------------------------------------------------------------
__global__ __launch_bounds__(128)
void flash_kernel(const float* __restrict__ Q, const float* __restrict__ K,
                  const float* __restrict__ V, float* __restrict__ O)
{
    extern __shared__ float sm[];
    float* sQ = sm;                 // 64*65
    float* sK = sm + 64*65;         // 64*65  (aliased by sP)
    float* sV = sm + 2*64*65;       // 64*64
    float* sP = sK;

    const int qb  = blockIdx.x;
    const int bh  = blockIdx.y;
    const int tid = threadIdx.x;
    const int tr  = tid >> 3;       // 0..15
    const int tc  = tid & 7;        // 0..7
    const int r0  = tr*4;
    const int c0  = tc*8;

    // load Q tile
    const float* Qg = Q + ((size_t)bh*SEQ + qb*64)*HD;
    for (int idx = tid; idx < 64*64; idx += 128) {
        const int r = idx >> 6, d = idx & 63;
        sQ[r*65 + d] = Qg[r*64 + d];
    }

    float m[4], l[4], acc[4][8];
    #pragma unroll
    for (int i = 0; i < 4; i++) {
        m[i] = -1e30f; l[i] = 0.f;
        #pragma unroll
        for (int j = 0; j < 8; j++) acc[i][j] = 0.f;
    }

    for (int kb = 0; kb <= qb; kb++) {
        __syncthreads();   // prior P / V reads complete before refill
        const float* Kg = K + ((size_t)bh*SEQ + kb*64)*HD;
        const float* Vg = V + ((size_t)bh*SEQ + kb*64)*HD;
        for (int idx = tid; idx < 64*64; idx += 128) {
            const int r = idx >> 6, d = idx & 63;
            sK[r*65 + d] = Kg[r*64 + d];
            sV[r*64 + d] = Vg[r*64 + d];
        }
        __syncthreads();

        // S = Q @ K^T (this thread's 4x8 tile)
        float s[4][8];
        #pragma unroll
        for (int i = 0; i < 4; i++)
            #pragma unroll
            for (int j = 0; j < 8; j++) s[i][j] = 0.f;

        #pragma unroll 4
        for (int d = 0; d < 64; d++) {
            float qv[4], kv[8];
            #pragma unroll
            for (int i = 0; i < 4; i++) qv[i] = sQ[(r0+i)*65 + d];
            #pragma unroll
            for (int j = 0; j < 8; j++) kv[j] = sK[(c0+j)*65 + d];
            #pragma unroll
            for (int i = 0; i < 4; i++)
                #pragma unroll
                for (int j = 0; j < 8; j++)
                    s[i][j] += qv[i] * kv[j];
        }

        // scale + causal mask
        const bool diag = (kb == qb);
        #pragma unroll
        for (int i = 0; i < 4; i++)
            #pragma unroll
            for (int j = 0; j < 8; j++) {
                s[i][j] *= 0.125f;   // 1/sqrt(64)
                if (diag && (c0 + j > r0 + i)) s[i][j] = -1e30f;
            }

        // online softmax
        float nm[4], rl[4];
        #pragma unroll
        for (int i = 0; i < 4; i++) {
            float mx = s[i][0];
            #pragma unroll
            for (int j = 1; j < 8; j++) mx = fmaxf(mx, s[i][j]);
            #pragma unroll
            for (int o = 1; o < 8; o <<= 1)
                mx = fmaxf(mx, __shfl_xor_sync(0xffffffffu, mx, o));
            nm[i] = fmaxf(m[i], mx);
        }
        #pragma unroll
        for (int i = 0; i < 4; i++) {
            float sum = 0.f;
            #pragma unroll
            for (int j = 0; j < 8; j++) {
                s[i][j] = __expf(s[i][j] - nm[i]);
                sum += s[i][j];
            }
            #pragma unroll
            for (int o = 1; o < 8; o <<= 1)
                sum += __shfl_xor_sync(0xffffffffu, sum, o);
            rl[i] = sum;
        }
        #pragma unroll
        for (int i = 0; i < 4; i++) {
            const float alpha = __expf(m[i] - nm[i]);
            l[i] = l[i]*alpha + rl[i];
            m[i] = nm[i];
            #pragma unroll
            for (int j = 0; j < 8; j++) acc[i][j] *= alpha;
        }

        __syncthreads();   // all K reads done before overwriting sP (== sK)
        #pragma unroll
        for (int i = 0; i < 4; i++)
            #pragma unroll
            for (int j = 0; j < 8; j++)
                sP[(r0+i)*65 + c0 + j] = s[i][j];
        __syncthreads();

        // O += P @ V (this thread's 4 rows x 8 d-cols)
        #pragma unroll 4
        for (int c = 0; c < 64; c++) {
            float pv[4], vv[8];
            #pragma unroll
            for (int i = 0; i < 4; i++) pv[i] = sP[(r0+i)*65 + c];
            #pragma unroll
            for (int j = 0; j < 8; j++) vv[j] = sV[c*64 + c0 + j];
            #pragma unroll
            for (int i = 0; i < 4; i++)
                #pragma unroll
                for (int j = 0; j < 8; j++)
                    acc[i][j] += pv[i] * vv[j];
        }
    }

    // epilogue: O[b, s, h*64+d]
    const int b = bh >> 4, h = bh & 15;
    #pragma unroll
    for (int i = 0; i < 4; i++) {
        const int srow = qb*64 + r0 + i;
        const float inv = 1.f / l[i];
        const size_t base = ((size_t)b*SEQ + srow)*DIM + h*HD + c0;
        #pragma unroll
        for (int j = 0; j < 8; j++) O[base + j] = acc[i][j] * inv;
    }
}

// ---------------------------------------------------------------------------
// Launch
// ---------------------------------------------------------------------------
extern "C" void kernel_launch(void* const* d_in, const int* in_sizes, int n_in,
                              void* d_out, int out_size)
{
    const float* q  = (const float*)d_in[0];
    const float* k  = (const float*)d_in[1];
    const float* v  = (const float*)d_in[2];
    const float* wq = (const float*)d_in[3];
    const float* wk = (const float*)d_in[4];
    const float* wv = (const float*)d_in[5];
    const float* wo = (const float*)d_in[6];
    float* out = (float*)d_out;

    float *gq, *gk, *gv, *ga;
    cudaGetSymbolAddress((void**)&gq, g_q);
    cudaGetSymbolAddress((void**)&gk, g_k);
    cudaGetSymbolAddress((void**)&gv, g_v);
    cudaGetSymbolAddress((void**)&ga, g_attn);

    const dim3 gg(DIM/128, MTOT/128);
    const dim3 gb(256);

    gemm_kernel<1><<<gg, gb>>>(q, wq, gq, MTOT, DIM, DIM);
    gemm_kernel<1><<<gg, gb>>>(k, wk, gk, MTOT, DIM, DIM);
    gemm_kernel<1><<<gg, gb>>>(v, wv, gv, MTOT, DIM, DIM);

    const int FLASH_SMEM = (64*65*2 + 64*64) * (int)sizeof(float);  // 49664
    cudaFuncSetAttribute(flash_kernel,
                         cudaFuncAttributeMaxDynamicSharedMemorySize, FLASH_SMEM);
    flash_kernel<<<dim3(SEQ/64, BATCH*NH), 128, FLASH_SMEM>>>(gq, gk, gv, ga);

    gemm_kernel<0><<<gg, gb>>>(ga, wo, out, MTOT, DIM, DIM);
}

// round 3
// speedup vs baseline: 1.3269x; 1.3269x over previous
#include <cuda_runtime.h>
#include <cuda_bf16.h>
#include <cstdint>
#include <cstddef>
#include <math.h>

#define DIM    1024
#define NH     16
#define HD     64
#define BATCH  4
#define SEQ    2048
#define MTOT   (BATCH*SEQ)   // 8192

// ---------------------------------------------------------------------------
// Scratch (static __device__ arrays: allocation-free per harness rules)
// ---------------------------------------------------------------------------
__device__ float g_q[(size_t)BATCH*NH*SEQ*HD];   // [b,h,s,d]
__device__ float g_k[(size_t)BATCH*NH*SEQ*HD];
__device__ float g_v[(size_t)BATCH*NH*SEQ*HD];
__device__ float g_attn[(size_t)MTOT*DIM];       // [b,s,h*d]
// bf16 hi/lo staging, reused across the 4 GEMMs (stream-ordered)
__device__ __nv_bfloat16 g_ah[(size_t)MTOT*DIM];
__device__ __nv_bfloat16 g_al[(size_t)MTOT*DIM];
__device__ __nv_bfloat16 g_wh[(size_t)DIM*DIM];
__device__ __nv_bfloat16 g_wl[(size_t)DIM*DIM];

// ---------------------------------------------------------------------------
// fp32 -> (bf16 hi, bf16 lo) split.  x ≈ hi + lo to ~2^-18 relative.
// ---------------------------------------------------------------------------
__global__ __launch_bounds__(256)
void split_kernel(const float* __restrict__ x,
                  __nv_bfloat16* __restrict__ hi,
                  __nv_bfloat16* __restrict__ lo, int n4)
{
    int i = blockIdx.x*blockDim.x + threadIdx.x;
    if (i >= n4) return;
    float4 v = ((const float4*)x)[i];
    float vv[4] = {v.x, v.y, v.z, v.w};
    __nv_bfloat16 h[4], l[4];
    #pragma unroll
    for (int j = 0; j < 4; j++) {
        h[j] = __float2bfloat16(vv[j]);
        l[j] = __float2bfloat16(vv[j] - __bfloat162float(h[j]));
    }
    *reinterpret_cast<float2*>(hi + (size_t)4*i) = *reinterpret_cast<float2*>(h);
    *reinterpret_cast<float2*>(lo + (size_t)4*i) = *reinterpret_cast<float2*>(l);
}

// ---------------------------------------------------------------------------
// mma.sync helpers
// ---------------------------------------------------------------------------
__device__ __forceinline__ void ldsm_x4(uint32_t* r, uint32_t a) {
    asm volatile("ldmatrix.sync.aligned.m8n8.x4.shared.b16 {%0,%1,%2,%3}, [%4];"
        : "=r"(r[0]), "=r"(r[1]), "=r"(r[2]), "=r"(r[3]) : "r"(a));
}
__device__ __forceinline__ void ldsm_x4_t(uint32_t* r, uint32_t a) {
    asm volatile("ldmatrix.sync.aligned.m8n8.x4.trans.shared.b16 {%0,%1,%2,%3}, [%4];"
        : "=r"(r[0]), "=r"(r[1]), "=r"(r[2]), "=r"(r[3]) : "r"(a));
}
__device__ __forceinline__ void mma_bf16(float* c, const uint32_t* a, const uint32_t* b) {
    asm volatile("mma.sync.aligned.m16n8k16.row.col.f32.bf16.bf16.f32 "
        "{%0,%1,%2,%3}, {%4,%5,%6,%7}, {%8,%9}, {%0,%1,%2,%3};"
        : "+f"(c[0]), "+f"(c[1]), "+f"(c[2]), "+f"(c[3])
        : "r"(a[0]), "r"(a[1]), "r"(a[2]), "r"(a[3]), "r"(b[0]), "r"(b[1]));
}

// ---------------------------------------------------------------------------
// Compensated bf16 GEMM: C = Ah@Bh + Al@Bh + Ah@Bl   (~fp32-accurate)
// A,B row-major bf16 pairs; C fp32. 128x128 tile, BK=32, 256 thr (8 warps).
// Warp grid 4(m) x 2(n): warp tile 32x64; 2 m-frags x 8 n-frags of m16n8k16.
// MODE 0: C[m*N+n].  MODE 1: head-split -> C[((b*NH+h)*SEQ+s)*HD + d].
// ---------------------------------------------------------------------------
#define TBM 128
#define TBN 128
#define TBK 32
#define APAD 8
#define BPAD 8

template<int MODE>
__global__ __launch_bounds__(256)
void gemm_bf16c_kernel(const __nv_bfloat16* __restrict__ Ah,
                       const __nv_bfloat16* __restrict__ Al,
                       const __nv_bfloat16* __restrict__ Bh,
                       const __nv_bfloat16* __restrict__ Bl,
                       float* __restrict__ C, int M, int N, int K)
{
    __shared__ __align__(16) __nv_bfloat16 sAh[TBM][TBK+APAD];
    __shared__ __align__(16) __nv_bfloat16 sAl[TBM][TBK+APAD];
    __shared__ __align__(16) __nv_bfloat16 sBh[TBK][TBN+BPAD];
    __shared__ __align__(16) __nv_bfloat16 sBl[TBK][TBN+BPAD];

    const int tid  = threadIdx.x;
    const int lane = tid & 31;
    const int wid  = tid >> 5;
    const int wm   = wid & 3;            // rows wm*32
    const int wn   = wid >> 2;           // cols wn*64
    const int bm   = blockIdx.y, bn = blockIdx.x;

    float c[2][8][4];
    #pragma unroll
    for (int mi = 0; mi < 2; mi++)
        #pragma unroll
        for (int ni = 0; ni < 8; ni++)
            #pragma unroll
            for (int j = 0; j < 4; j++) c[mi][ni][j] = 0.f;

    for (int kt = 0; kt < K; kt += TBK) {
        // ---- stage tiles (each thread: 2 uint4 per array) ----
        #pragma unroll
        for (int i = 0; i < 2; i++) {
            const int lin = tid*2 + i;
            const int ar = lin >> 2, aq = (lin & 3) * 8;     // A: 128 rows x 4 quads
            const size_t ga = (size_t)(bm*TBM + ar)*K + kt + aq;
            *(uint4*)&sAh[ar][aq] = *(const uint4*)(Ah + ga);
            *(uint4*)&sAl[ar][aq] = *(const uint4*)(Al + ga);
            const int br = lin >> 4, bq = (lin & 15) * 8;    // B: 32 rows x 16 quads
            const size_t gb = (size_t)(kt + br)*N + bn*TBN + bq;
            *(uint4*)&sBh[br][bq] = *(const uint4*)(Bh + gb);
            *(uint4*)&sBl[br][bq] = *(const uint4*)(Bl + gb);
        }
        __syncthreads();

        #pragma unroll
        for (int ks = 0; ks < 2; ks++) {
            const int k0 = ks*16;
            uint32_t ah[2][4], al[2][4], bh[8][2], bl[8][2];
            #pragma unroll
            for (int mi = 0; mi < 2; mi++) {
                const int row = wm*32 + mi*16 + (lane & 15);
                const int col = k0 + (lane >> 4)*8;
                ldsm_x4(ah[mi], (uint32_t)__cvta_generic_to_shared(&sAh[row][col]));
                ldsm_x4(al[mi], (uint32_t)__cvta_generic_to_shared(&sAl[row][col]));
            }
            #pragma unroll
            for (int j = 0; j < 4; j++) {                    // each x4.trans covers 2 n-frags
                const int n0  = wn*64 + j*16;
                const int kr  = lane & 7, sel = lane >> 3;
                const int row = k0 + (sel & 1)*8 + kr;
                const int col = n0 + (sel >> 1)*8;
                uint32_t t[4];
                ldsm_x4_t(t, (uint32_t)__cvta_generic_to_shared(&sBh[row][col]));
                bh[2*j][0]=t[0]; bh[2*j][1]=t[1]; bh[2*j+1][0]=t[2]; bh[2*j+1][1]=t[3];
                ldsm_x4_t(t, (uint32_t)__cvta_generic_to_shared(&sBl[row][col]));
                bl[2*j][0]=t[0]; bl[2*j][1]=t[1]; bl[2*j+1][0]=t[2]; bl[2*j+1][1]=t[3];
            }
            #pragma unroll
            for (int mi = 0; mi < 2; mi++)
                #pragma unroll
                for (int ni = 0; ni < 8; ni++) {
                    mma_bf16(c[mi][ni], ah[mi], bh[ni]);
                    mma_bf16(c[mi][ni], al[mi], bh[ni]);
                    mma_bf16(c[mi][ni], ah[mi], bl[ni]);
                }
        }
        __syncthreads();
    }

    // ---- epilogue ----
    #pragma unroll
    for (int mi = 0; mi < 2; mi++)
        #pragma unroll
        for (int ni = 0; ni < 8; ni++) {
            const int row0 = bm*TBM + wm*32 + mi*16 + (lane >> 2);
            const int ncol = bn*TBN + wn*64 + ni*8 + (lane & 3)*2;
            #pragma unroll
            for (int half = 0; half < 2; half++) {
                const int m = row0 + half*8;
                const float2 v = make_float2(c[mi][ni][2*half], c[mi][ni][2*half+1]);
                if (MODE == 0) {
                    *(float2*)&C[(size_t)m*N + ncol] = v;
                } else {
                    const int b = m >> 11, s = m & (SEQ-1);
                    const int h = ncol >> 6, d0 = ncol & 63;
                    *(float2*)&C[(((size_t)b*NH + h)*SEQ + s)*HD + d0] = v;
                }
            }
        }
}

// ---------------------------------------------------------------------------
// Causal flash attention, fp32 (unchanged). Br=Bc=64, D=64.
// ---------------------------------------------------------------------------
__global__ __launch_bounds__(128)
void flash_kernel(const float* __restrict__ Q, const float* __restrict__ K,
                  const float* __restrict__ V, float* __restrict__ O)
{
    extern __shared__ float sm[];
    float* sQ = sm;                 // 64*65
    float* sK = sm + 64*65;         // 64*65  (aliased by sP)
    float* sV = sm + 2*64*65;       // 64*64
    float* sP = sK;

    const int qb  = blockIdx.x;
    const int bh  = blockIdx.y;
    const int tid = threadIdx.x;
    const int tr  = tid >> 3;
    const int tc  = tid & 7;
    const int r0  = tr*4;
    const int c0  = tc*8;

    const float* Qg = Q + ((size_t)bh*SEQ + qb*64)*HD;
    for (int idx = tid; idx < 64*64; idx += 128) {
        const int r = idx >> 6, d = idx & 63;
        sQ[r*65 + d] = Qg[r*64 + d];
    }

    float m[4], l[4], acc[4][8];
    #pragma unroll
    for (int i = 0; i < 4; i++) {
        m[i] = -1e30f; l[i] = 0.f;
        #pragma unroll
        for (int j = 0; j < 8; j++) acc[i][j] = 0.f;
    }

    for (int kb = 0; kb <= qb; kb++) {
        __syncthreads();
        const float* Kg = K + ((size_t)bh*SEQ + kb*64)*HD;
        const float* Vg = V + ((size_t)bh*SEQ + kb*64)*HD;
        for (int idx = tid; idx < 64*64; idx += 128) {
            const int r = idx >> 6, d = idx & 63;
            sK[r*65 + d] = Kg[r*64 + d];
            sV[r*64 + d] = Vg[r*64 + d];
        }
        __syncthreads();

        float s[4][8];
        #pragma unroll
        for (int i = 0; i < 4; i++)
            #pragma unroll
            for (int j = 0; j < 8; j++) s[i][j] = 0.f;

        #pragma unroll 4
        for (int d = 0; d < 64; d++) {
            float qv[4], kv[8];
            #pragma unroll
            for (int i = 0; i < 4; i++) qv[i] = sQ[(r0+i)*65 + d];
            #pragma unroll
            for (int j = 0; j < 8; j++) kv[j] = sK[(c0+j)*65 + d];
            #pragma unroll
            for (int i = 0; i < 4; i++)
                #pragma unroll
                for (int j = 0; j < 8; j++)
                    s[i][j] += qv[i] * kv[j];
        }

        const bool diag = (kb == qb);
        #pragma unroll
        for (int i = 0; i < 4; i++)
            #pragma unroll
            for (int j = 0; j < 8; j++) {
                s[i][j] *= 0.125f;
                if (diag && (c0 + j > r0 + i)) s[i][j] = -1e30f;
            }

        float nm[4], rl[4];
        #pragma unroll
        for (int i = 0; i < 4; i++) {
            float mx = s[i][0];
            #pragma unroll
            for (int j = 1; j < 8; j++) mx = fmaxf(mx, s[i][j]);
            #pragma unroll
            for (int o = 1; o < 8; o <<= 1)
                mx = fmaxf(mx, __shfl_xor_sync(0xffffffffu, mx, o));
            nm[i] = fmaxf(m[i], mx);
        }
        #pragma unroll
        for (int i = 0; i < 4; i++) {
            float sum = 0.f;
            #pragma unroll
            for (int j = 0; j < 8; j++) {
                s[i][j] = __expf(s[i][j] - nm[i]);
                sum += s[i][j];
            }
            #pragma unroll
            for (int o = 1; o < 8; o <<= 1)
                sum += __shfl_xor_sync(0xffffffffu, sum, o);
            rl[i] = sum;
        }
        #pragma unroll
        for (int i = 0; i < 4; i++) {
            const float alpha = __expf(m[i] - nm[i]);
            l[i] = l[i]*alpha + rl[i];
            m[i] = nm[i];
            #pragma unroll
            for (int j = 0; j < 8; j++) acc[i][j] *= alpha;
        }

        __syncthreads();
        #pragma unroll
        for (int i = 0; i < 4; i++)
            #pragma unroll
            for (int j = 0; j < 8; j++)
                sP[(r0+i)*65 + c0 + j] = s[i][j];
        __syncthreads();

        #pragma unroll 4
        for (int cc = 0; cc < 64; cc++) {
            float pv[4], vv[8];
            #pragma unroll
            for (int i = 0; i < 4; i++) pv[i] = sP[(r0+i)*65 + cc];
            #pragma unroll
            for (int j = 0; j < 8; j++) vv[j] = sV[cc*64 + c0 + j];
            #pragma unroll
            for (int i = 0; i < 4; i++)
                #pragma unroll
                for (int j = 0; j < 8; j++)
                    acc[i][j] += pv[i] * vv[j];
        }
    }

    const int b = bh >> 4, h = bh & 15;
    #pragma unroll
    for (int i = 0; i < 4; i++) {
        const int srow = qb*64 + r0 + i;
        const float inv = 1.f / l[i];
        const size_t base = ((size_t)b*SEQ + srow)*DIM + h*HD + c0;
        #pragma unroll
        for (int j = 0; j < 8; j++) O[base + j] = acc[i][j] * inv;
    }
}

// ---------------------------------------------------------------------------
// Launch
// ---------------------------------------------------------------------------
extern "C" void kernel_launch(void* const* d_in, const int* in_sizes, int n_in,
                              void* d_out, int out_size)
{
    const float* q  = (const float*)d_in[0];
    const float* k  = (const float*)d_in[1];
    const float* v  = (const float*)d_in[2];
    const float* wq = (const float*)d_in[3];
    const float* wk = (const float*)d_in[4];
    const float* wv = (const float*)d_in[5];
    const float* wo = (const float*)d_in[6];
    float* out = (float*)d_out;

    float *gq, *gk, *gv, *ga;
    __nv_bfloat16 *ah, *al, *wh, *wl;
    cudaGetSymbolAddress((void**)&gq, g_q);
    cudaGetSymbolAddress((void**)&gk, g_k);
    cudaGetSymbolAddress((void**)&gv, g_v);
    cudaGetSymbolAddress((void**)&ga, g_attn);
    cudaGetSymbolAddress((void**)&ah, g_ah);
    cudaGetSymbolAddress((void**)&al, g_al);
    cudaGetSymbolAddress((void**)&wh, g_wh);
    cudaGetSymbolAddress((void**)&wl, g_wl);

    const int ACT4 = MTOT*DIM/4, W4 = DIM*DIM/4;
    const dim3 gg(DIM/TBN, MTOT/TBM);   // (8, 64)

    // Q projection
    split_kernel<<<ACT4/256, 256>>>(q,  ah, al, ACT4);
    split_kernel<<<W4/256,  256>>>(wq, wh, wl, W4);
    gemm_bf16c_kernel<1><<<gg, 256>>>(ah, al, wh, wl, gq, MTOT, DIM, DIM);
    // K projection
    split_kernel<<<ACT4/256, 256>>>(k,  ah, al, ACT4);
    split_kernel<<<W4/256,  256>>>(wk, wh, wl, W4);
    gemm_bf16c_kernel<1><<<gg, 256>>>(ah, al, wh, wl, gk, MTOT, DIM, DIM);
    // V projection
    split_kernel<<<ACT4/256, 256>>>(v,  ah, al, ACT4);
    split_kernel<<<W4/256,  256>>>(wv, wh, wl, W4);
    gemm_bf16c_kernel<1><<<gg, 256>>>(ah, al, wh, wl, gv, MTOT, DIM, DIM);

    // Attention
    const int FLASH_SMEM = (64*65*2 + 64*64) * (int)sizeof(float);  // 49664
    cudaFuncSetAttribute(flash_kernel,
                         cudaFuncAttributeMaxDynamicSharedMemorySize, FLASH_SMEM);
    flash_kernel<<<dim3(SEQ/64, BATCH*NH), 128, FLASH_SMEM>>>(gq, gk, gv, ga);

    // Output projection
    split_kernel<<<ACT4/256, 256>>>(ga, ah, al, ACT4);
    split_kernel<<<W4/256,  256>>>(wo, wh, wl, W4);
    gemm_bf16c_kernel<0><<<gg, 256>>>(ah, al, wh, wl, out, MTOT, DIM, DIM);
}

// round 4
// speedup vs baseline: 2.6474x; 1.9952x over previous
#include <cuda_runtime.h>
#include <cuda_bf16.h>
#include <cstdint>
#include <cstddef>
#include <math.h>

#define DIM    1024
#define NH     16
#define HD     64
#define BATCH  4
#define SEQ    2048
#define MTOT   (BATCH*SEQ)   // 8192

// ---------------------------------------------------------------------------
// Scratch (static __device__ arrays: allocation-free per harness rules)
// ---------------------------------------------------------------------------
__device__ __nv_bfloat16 g_xh[(size_t)MTOT*DIM];  // act hi (q/k/v input splits)
__device__ __nv_bfloat16 g_xl[(size_t)MTOT*DIM];  // act lo
__device__ __nv_bfloat16 g_wh[(size_t)DIM*DIM];   // weight hi (reused per GEMM)
__device__ __nv_bfloat16 g_wl[(size_t)DIM*DIM];   // weight lo
__device__ __nv_bfloat16 g_qh[(size_t)MTOT*DIM];  // [bh, s, d] bf16 hi/lo
__device__ __nv_bfloat16 g_ql[(size_t)MTOT*DIM];
__device__ __nv_bfloat16 g_kh[(size_t)MTOT*DIM];
__device__ __nv_bfloat16 g_kl[(size_t)MTOT*DIM];
__device__ __nv_bfloat16 g_vh[(size_t)MTOT*DIM];
__device__ __nv_bfloat16 g_vl[(size_t)MTOT*DIM];
__device__ __nv_bfloat16 g_oh[(size_t)MTOT*DIM];  // attn out [b,s,h*d] hi/lo
__device__ __nv_bfloat16 g_ol[(size_t)MTOT*DIM];

// ---------------------------------------------------------------------------
// helpers
// ---------------------------------------------------------------------------
__device__ __forceinline__ void split2(float x, float y, uint32_t& hi, uint32_t& lo) {
    __nv_bfloat162 h, l;
    h.x = __float2bfloat16(x);
    h.y = __float2bfloat16(y);
    l.x = __float2bfloat16(x - __bfloat162float(h.x));
    l.y = __float2bfloat16(y - __bfloat162float(h.y));
    hi = *reinterpret_cast<uint32_t*>(&h);
    lo = *reinterpret_cast<uint32_t*>(&l);
}
__device__ __forceinline__ void ldsm_x4(uint32_t* r, const void* p) {
    uint32_t a = (uint32_t)__cvta_generic_to_shared(p);
    asm volatile("ldmatrix.sync.aligned.m8n8.x4.shared.b16 {%0,%1,%2,%3}, [%4];"
        : "=r"(r[0]), "=r"(r[1]), "=r"(r[2]), "=r"(r[3]) : "r"(a));
}
__device__ __forceinline__ void ldsm_x4_t(uint32_t* r, const void* p) {
    uint32_t a = (uint32_t)__cvta_generic_to_shared(p);
    asm volatile("ldmatrix.sync.aligned.m8n8.x4.trans.shared.b16 {%0,%1,%2,%3}, [%4];"
        : "=r"(r[0]), "=r"(r[1]), "=r"(r[2]), "=r"(r[3]) : "r"(a));
}
__device__ __forceinline__ void mma_bf16(float* c, const uint32_t* a, const uint32_t* b) {
    asm volatile("mma.sync.aligned.m16n8k16.row.col.f32.bf16.bf16.f32 "
        "{%0,%1,%2,%3}, {%4,%5,%6,%7}, {%8,%9}, {%0,%1,%2,%3};"
        : "+f"(c[0]), "+f"(c[1]), "+f"(c[2]), "+f"(c[3])
        : "r"(a[0]), "r"(a[1]), "r"(a[2]), "r"(a[3]), "r"(b[0]), "r"(b[1]));
}
__device__ __forceinline__ void cp16(void* s, const void* g) {
    uint32_t sa = (uint32_t)__cvta_generic_to_shared(s);
    asm volatile("cp.async.cg.shared.global [%0], [%1], 16;" :: "r"(sa), "l"(g));
}
__device__ __forceinline__ void cp_commit() {
    asm volatile("cp.async.commit_group;" ::: "memory");
}
template<int N>
__device__ __forceinline__ void cp_wait() {
    asm volatile("cp.async.wait_group %0;" :: "n"(N) : "memory");
}

// ---------------------------------------------------------------------------
// fp32 -> (bf16 hi, bf16 lo) split.
// ---------------------------------------------------------------------------
__global__ __launch_bounds__(256)
void split_kernel(const float* __restrict__ x,
                  __nv_bfloat16* __restrict__ hi,
                  __nv_bfloat16* __restrict__ lo, int n4)
{
    int i = blockIdx.x*blockDim.x + threadIdx.x;
    if (i >= n4) return;
    float4 v = ((const float4*)x)[i];
    uint32_t h0, l0, h1, l1;
    split2(v.x, v.y, h0, l0);
    split2(v.z, v.w, h1, l1);
    uint2 hh = make_uint2(h0, h1), ll = make_uint2(l0, l1);
    *reinterpret_cast<uint2*>(hi + (size_t)4*i) = hh;
    *reinterpret_cast<uint2*>(lo + (size_t)4*i) = ll;
}

// ---------------------------------------------------------------------------
// Compensated bf16 GEMM, 2-stage cp.async pipeline.
// C = Ah@Bh + Al@Bh + Ah@Bl.  128x128 tile, BK=32, 256 thr.
// MODE 0: fp32 C[m*N+n].
// MODE 1: bf16 hi/lo head-split -> Ch/Cl[((b*NH+h)*SEQ+s)*HD + d].
// ---------------------------------------------------------------------------
#define TBK     32
#define A_STR   40      // TBK + 8
#define B_STR   136     // 128 + 8
#define A_SZ    (128*A_STR)       // 5120 elems
#define B_SZ    (32*B_STR)        // 4352 elems
#define STG_SZ  (2*A_SZ + 2*B_SZ) // 18944 elems
#define GEMM_SMEM (2*STG_SZ*2)    // bytes: 75776

template<int MODE>
__global__ __launch_bounds__(256)
void gemm_bf16c_kernel(const __nv_bfloat16* __restrict__ Ah,
                       const __nv_bfloat16* __restrict__ Al,
                       const __nv_bfloat16* __restrict__ Bh,
                       const __nv_bfloat16* __restrict__ Bl,
                       float* __restrict__ C,
                       __nv_bfloat16* __restrict__ Ch,
                       __nv_bfloat16* __restrict__ Cl,
                       int M, int N, int K)
{
    extern __shared__ __nv_bfloat16 smem[];

    const int tid  = threadIdx.x;
    const int lane = tid & 31;
    const int wid  = tid >> 5;
    const int wm   = wid & 3;
    const int wn   = wid >> 2;
    const int bm   = blockIdx.y, bn = blockIdx.x;

    // per-thread load coordinates
    const int lin0 = tid*2;
    const int ar0 = lin0 >> 2,  aq0 = (lin0 & 3) * 8;
    const int ar1 = ar0,        aq1 = ((lin0+1) & 3) * 8;   // lin0 even -> same row
    const int br0 = lin0 >> 4,  bq0 = (lin0 & 15) * 8;
    const int br1 = (lin0+1) >> 4, bq1 = ((lin0+1) & 15) * 8;

    float c[2][8][4];
    #pragma unroll
    for (int mi = 0; mi < 2; mi++)
        #pragma unroll
        for (int ni = 0; ni < 8; ni++)
            #pragma unroll
            for (int j = 0; j < 4; j++) c[mi][ni][j] = 0.f;

    const int NT = K / TBK;

    // ---- stage issue helper (macro-free, inlined twice) ----
    auto issue = [&](int st, int kt) {
        __nv_bfloat16* aH = smem + st*STG_SZ;
        __nv_bfloat16* aL = aH + A_SZ;
        __nv_bfloat16* bH = aL + A_SZ;
        __nv_bfloat16* bL = bH + B_SZ;
        cp16(aH + ar0*A_STR + aq0, Ah + (size_t)(bm*128 + ar0)*K + kt + aq0);
        cp16(aH + ar1*A_STR + aq1, Ah + (size_t)(bm*128 + ar1)*K + kt + aq1);
        cp16(aL + ar0*A_STR + aq0, Al + (size_t)(bm*128 + ar0)*K + kt + aq0);
        cp16(aL + ar1*A_STR + aq1, Al + (size_t)(bm*128 + ar1)*K + kt + aq1);
        cp16(bH + br0*B_STR + bq0, Bh + (size_t)(kt + br0)*N + bn*128 + bq0);
        cp16(bH + br1*B_STR + bq1, Bh + (size_t)(kt + br1)*N + bn*128 + bq1);
        cp16(bL + br0*B_STR + bq0, Bl + (size_t)(kt + br0)*N + bn*128 + bq0);
        cp16(bL + br1*B_STR + bq1, Bl + (size_t)(kt + br1)*N + bn*128 + bq1);
    };

    issue(0, 0);
    cp_commit();

    for (int it = 0; it < NT; it++) {
        const int ktn = (it+1 < NT) ? (it+1)*TBK : (NT-1)*TBK;  // dummy reload on last
        issue((it+1) & 1, ktn);
        cp_commit();
        cp_wait<1>();
        __syncthreads();

        const int st = it & 1;
        __nv_bfloat16* aH = smem + st*STG_SZ;
        __nv_bfloat16* aL = aH + A_SZ;
        __nv_bfloat16* bH = aL + A_SZ;
        __nv_bfloat16* bL = bH + B_SZ;

        #pragma unroll
        for (int ks = 0; ks < 2; ks++) {
            const int k0 = ks*16;
            uint32_t ah[2][4], al[2][4], bh[8][2], bl[8][2];
            #pragma unroll
            for (int mi = 0; mi < 2; mi++) {
                const int row = wm*32 + mi*16 + (lane & 15);
                const int col = k0 + (lane >> 4)*8;
                ldsm_x4(ah[mi], aH + row*A_STR + col);
                ldsm_x4(al[mi], aL + row*A_STR + col);
            }
            #pragma unroll
            for (int j = 0; j < 4; j++) {
                const int n0  = wn*64 + j*16;
                const int kr  = lane & 7, sel = lane >> 3;
                const int row = k0 + (sel & 1)*8 + kr;
                const int col = n0 + (sel >> 1)*8;
                uint32_t t[4];
                ldsm_x4_t(t, bH + row*B_STR + col);
                bh[2*j][0]=t[0]; bh[2*j][1]=t[1]; bh[2*j+1][0]=t[2]; bh[2*j+1][1]=t[3];
                ldsm_x4_t(t, bL + row*B_STR + col);
                bl[2*j][0]=t[0]; bl[2*j][1]=t[1]; bl[2*j+1][0]=t[2]; bl[2*j+1][1]=t[3];
            }
            #pragma unroll
            for (int mi = 0; mi < 2; mi++)
                #pragma unroll
                for (int ni = 0; ni < 8; ni++) {
                    mma_bf16(c[mi][ni], ah[mi], bh[ni]);
                    mma_bf16(c[mi][ni], al[mi], bh[ni]);
                    mma_bf16(c[mi][ni], ah[mi], bl[ni]);
                }
        }
        __syncthreads();
    }

    // ---- epilogue ----
    #pragma unroll
    for (int mi = 0; mi < 2; mi++)
        #pragma unroll
        for (int ni = 0; ni < 8; ni++) {
            const int row0 = bm*128 + wm*32 + mi*16 + (lane >> 2);
            const int ncol = bn*128 + wn*64 + ni*8 + (lane & 3)*2;
            #pragma unroll
            for (int half = 0; half < 2; half++) {
                const int m = row0 + half*8;
                const float x = c[mi][ni][2*half], y = c[mi][ni][2*half+1];
                if (MODE == 0) {
                    *(float2*)&C[(size_t)m*N + ncol] = make_float2(x, y);
                } else {
                    const int b = m >> 11, s = m & (SEQ-1);
                    const int h = ncol >> 6, d0 = ncol & 63;
                    const size_t idx = (((size_t)b*NH + h)*SEQ + s)*HD + d0;
                    uint32_t hi, lo;
                    split2(x, y, hi, lo);
                    *reinterpret_cast<uint32_t*>(Ch + idx) = hi;
                    *reinterpret_cast<uint32_t*>(Cl + idx) = lo;
                }
            }
        }
}

// ---------------------------------------------------------------------------
// Tensor-core causal flash attention. Br=Bc=64, D=64, 4 warps (16 rows each).
// Q/K/V in bf16 hi/lo; S and O accumulated fp32; P hi/lo split in registers.
// smem: 6 tiles of 64x72 bf16 = 55296 B.
// ---------------------------------------------------------------------------
#define F_STR 72
#define F_TSZ (64*F_STR)
#define FLASH_SMEM (6*F_TSZ*2)

__global__ __launch_bounds__(128)
void flash_mma_kernel(const __nv_bfloat16* __restrict__ Qh, const __nv_bfloat16* __restrict__ Ql,
                      const __nv_bfloat16* __restrict__ Kh, const __nv_bfloat16* __restrict__ Kl,
                      const __nv_bfloat16* __restrict__ Vh, const __nv_bfloat16* __restrict__ Vl,
                      __nv_bfloat16* __restrict__ Oh, __nv_bfloat16* __restrict__ Ol)
{
    extern __shared__ __nv_bfloat16 fs[];
    __nv_bfloat16* sQh = fs;
    __nv_bfloat16* sQl = fs + F_TSZ;
    __nv_bfloat16* sKh = fs + 2*F_TSZ;
    __nv_bfloat16* sKl = fs + 3*F_TSZ;
    __nv_bfloat16* sVh = fs + 4*F_TSZ;
    __nv_bfloat16* sVl = fs + 5*F_TSZ;

    const int qb   = blockIdx.x;
    const int bh   = blockIdx.y;
    const int tid  = threadIdx.x;
    const int lane = tid & 31;
    const int w    = tid >> 5;
    const int m0w  = w*16;

    // ---- load Q tile ----
    {
        const size_t gbase = ((size_t)bh*SEQ + qb*64)*HD;
        for (int i = tid; i < 512; i += 128) {
            const int row = i >> 3, cq = (i & 7)*8;
            *(uint4*)&sQh[row*F_STR + cq] = *(const uint4*)(Qh + gbase + row*64 + cq);
            *(uint4*)&sQl[row*F_STR + cq] = *(const uint4*)(Ql + gbase + row*64 + cq);
        }
    }
    __syncthreads();

    // Q fragments (held in regs for the whole kernel)
    uint32_t qfh[4][4], qfl[4][4];
    #pragma unroll
    for (int ks = 0; ks < 4; ks++) {
        const int row = m0w + (lane & 15);
        const int col = ks*16 + (lane >> 4)*8;
        ldsm_x4(qfh[ks], sQh + row*F_STR + col);
        ldsm_x4(qfl[ks], sQl + row*F_STR + col);
    }

    float mr0 = -1e30f, mr1 = -1e30f, lr0 = 0.f, lr1 = 0.f;
    float o[8][4];
    #pragma unroll
    for (int j = 0; j < 8; j++)
        #pragma unroll
        for (int t = 0; t < 4; t++) o[j][t] = 0.f;

    for (int kb = 0; kb <= qb; kb++) {
        __syncthreads();
        {
            const size_t gbase = ((size_t)bh*SEQ + kb*64)*HD;
            for (int i = tid; i < 512; i += 128) {
                const int row = i >> 3, cq = (i & 7)*8;
                const size_t g = gbase + row*64 + cq;
                *(uint4*)&sKh[row*F_STR + cq] = *(const uint4*)(Kh + g);
                *(uint4*)&sKl[row*F_STR + cq] = *(const uint4*)(Kl + g);
                *(uint4*)&sVh[row*F_STR + cq] = *(const uint4*)(Vh + g);
                *(uint4*)&sVl[row*F_STR + cq] = *(const uint4*)(Vl + g);
            }
        }
        __syncthreads();

        // ---- S = Q @ K^T ----
        float s[8][4];
        #pragma unroll
        for (int j = 0; j < 8; j++)
            #pragma unroll
            for (int t = 0; t < 4; t++) s[j][t] = 0.f;

        #pragma unroll
        for (int ks = 0; ks < 4; ks++) {
            uint32_t kfh[8][2], kfl[8][2];
            #pragma unroll
            for (int njp = 0; njp < 4; njp++) {
                const int row = njp*16 + ((lane & 16) ? 8 : 0) + (lane & 7);
                const int col = ks*16 + ((lane & 8) ? 8 : 0);
                uint32_t t[4];
                ldsm_x4(t, sKh + row*F_STR + col);
                kfh[2*njp][0]=t[0]; kfh[2*njp][1]=t[1]; kfh[2*njp+1][0]=t[2]; kfh[2*njp+1][1]=t[3];
                ldsm_x4(t, sKl + row*F_STR + col);
                kfl[2*njp][0]=t[0]; kfl[2*njp][1]=t[1]; kfl[2*njp+1][0]=t[2]; kfl[2*njp+1][1]=t[3];
            }
            #pragma unroll
            for (int nj = 0; nj < 8; nj++) {
                mma_bf16(s[nj], qfh[ks], kfh[nj]);
                mma_bf16(s[nj], qfl[ks], kfh[nj]);
                mma_bf16(s[nj], qfh[ks], kfl[nj]);
            }
        }

        // scale + causal mask
        const bool diag = (kb == qb);
        #pragma unroll
        for (int j = 0; j < 8; j++)
            #pragma unroll
            for (int t = 0; t < 4; t++) {
                s[j][t] *= 0.125f;
                if (diag) {
                    const int col = j*8 + (lane & 3)*2 + (t & 1);
                    const int row = m0w + (lane >> 2) + ((t >> 1)*8);
                    if (col > row) s[j][t] = -1e30f;
                }
            }

        // ---- online softmax ----
        float mx0 = s[0][0], mx1 = s[0][2];
        #pragma unroll
        for (int j = 0; j < 8; j++) {
            mx0 = fmaxf(mx0, fmaxf(s[j][0], s[j][1]));
            mx1 = fmaxf(mx1, fmaxf(s[j][2], s[j][3]));
        }
        #pragma unroll
        for (int off = 1; off < 4; off <<= 1) {
            mx0 = fmaxf(mx0, __shfl_xor_sync(0xffffffffu, mx0, off));
            mx1 = fmaxf(mx1, __shfl_xor_sync(0xffffffffu, mx1, off));
        }
        const float nm0 = fmaxf(mr0, mx0), nm1 = fmaxf(mr1, mx1);

        float sum0 = 0.f, sum1 = 0.f;
        #pragma unroll
        for (int j = 0; j < 8; j++) {
            s[j][0] = __expf(s[j][0] - nm0);
            s[j][1] = __expf(s[j][1] - nm0);
            s[j][2] = __expf(s[j][2] - nm1);
            s[j][3] = __expf(s[j][3] - nm1);
            sum0 += s[j][0] + s[j][1];
            sum1 += s[j][2] + s[j][3];
        }
        #pragma unroll
        for (int off = 1; off < 4; off <<= 1) {
            sum0 += __shfl_xor_sync(0xffffffffu, sum0, off);
            sum1 += __shfl_xor_sync(0xffffffffu, sum1, off);
        }
        const float a0 = __expf(mr0 - nm0), a1 = __expf(mr1 - nm1);
        lr0 = lr0*a0 + sum0;  lr1 = lr1*a1 + sum1;
        mr0 = nm0;            mr1 = nm1;
        #pragma unroll
        for (int j = 0; j < 8; j++) {
            o[j][0] *= a0; o[j][1] *= a0; o[j][2] *= a1; o[j][3] *= a1;
        }

        // ---- P -> bf16 hi/lo A-fragments (in registers) ----
        uint32_t aPh[4][4], aPl[4][4];
        #pragma unroll
        for (int ks = 0; ks < 4; ks++) {
            split2(s[2*ks][0],   s[2*ks][1],   aPh[ks][0], aPl[ks][0]);
            split2(s[2*ks][2],   s[2*ks][3],   aPh[ks][1], aPl[ks][1]);
            split2(s[2*ks+1][0], s[2*ks+1][1], aPh[ks][2], aPl[ks][2]);
            split2(s[2*ks+1][2], s[2*ks+1][3], aPh[ks][3], aPl[ks][3]);
        }

        // ---- O += P @ V ----
        #pragma unroll
        for (int ks = 0; ks < 4; ks++) {
            uint32_t vfh[8][2], vfl[8][2];
            #pragma unroll
            for (int njp = 0; njp < 4; njp++) {
                const int sel = lane >> 3, r = lane & 7;
                const int row = ks*16 + (sel & 1)*8 + r;
                const int col = njp*16 + (sel >> 1)*8;
                uint32_t t[4];
                ldsm_x4_t(t, sVh + row*F_STR + col);
                vfh[2*njp][0]=t[0]; vfh[2*njp][1]=t[1]; vfh[2*njp+1][0]=t[2]; vfh[2*njp+1][1]=t[3];
                ldsm_x4_t(t, sVl + row*F_STR + col);
                vfl[2*njp][0]=t[0]; vfl[2*njp][1]=t[1]; vfl[2*njp+1][0]=t[2]; vfl[2*njp+1][1]=t[3];
            }
            #pragma unroll
            for (int nj = 0; nj < 8; nj++) {
                mma_bf16(o[nj], aPh[ks], vfh[nj]);
                mma_bf16(o[nj], aPl[ks], vfh[nj]);
                mma_bf16(o[nj], aPh[ks], vfl[nj]);
            }
        }
    }

    // ---- epilogue: O/l -> bf16 hi/lo at [b, s, h*64+d] ----
    const int b = bh >> 4, h = bh & 15;
    const float inv0 = 1.f / lr0, inv1 = 1.f / lr1;
    const int srow0 = qb*64 + m0w + (lane >> 2);
    const int srow1 = srow0 + 8;
    #pragma unroll
    for (int j = 0; j < 8; j++) {
        const int col = j*8 + (lane & 3)*2;
        uint32_t hi, lo;
        split2(o[j][0]*inv0, o[j][1]*inv0, hi, lo);
        size_t idx = ((size_t)b*SEQ + srow0)*DIM + h*HD + col;
        *reinterpret_cast<uint32_t*>(Oh + idx) = hi;
        *reinterpret_cast<uint32_t*>(Ol + idx) = lo;
        split2(o[j][2]*inv1, o[j][3]*inv1, hi, lo);
        idx = ((size_t)b*SEQ + srow1)*DIM + h*HD + col;
        *reinterpret_cast<uint32_t*>(Oh + idx) = hi;
        *reinterpret_cast<uint32_t*>(Ol + idx) = lo;
    }
}

// ---------------------------------------------------------------------------
// Launch
// ---------------------------------------------------------------------------
extern "C" void kernel_launch(void* const* d_in, const int* in_sizes, int n_in,
                              void* d_out, int out_size)
{
    const float* q  = (const float*)d_in[0];
    const float* k  = (const float*)d_in[1];
    const float* v  = (const float*)d_in[2];
    const float* wq = (const float*)d_in[3];
    const float* wk = (const float*)d_in[4];
    const float* wv = (const float*)d_in[5];
    const float* wo = (const float*)d_in[6];
    float* out = (float*)d_out;

    __nv_bfloat16 *xh, *xl, *wh, *wl, *qh, *ql, *kh, *kl, *vh, *vl, *oh, *ol;
    cudaGetSymbolAddress((void**)&xh, g_xh);
    cudaGetSymbolAddress((void**)&xl, g_xl);
    cudaGetSymbolAddress((void**)&wh, g_wh);
    cudaGetSymbolAddress((void**)&wl, g_wl);
    cudaGetSymbolAddress((void**)&qh, g_qh);
    cudaGetSymbolAddress((void**)&ql, g_ql);
    cudaGetSymbolAddress((void**)&kh, g_kh);
    cudaGetSymbolAddress((void**)&kl, g_kl);
    cudaGetSymbolAddress((void**)&vh, g_vh);
    cudaGetSymbolAddress((void**)&vl, g_vl);
    cudaGetSymbolAddress((void**)&oh, g_oh);
    cudaGetSymbolAddress((void**)&ol, g_ol);

    static bool attr_done = false;
    if (!attr_done) {
        cudaFuncSetAttribute(gemm_bf16c_kernel<0>,
                             cudaFuncAttributeMaxDynamicSharedMemorySize, GEMM_SMEM);
        cudaFuncSetAttribute(gemm_bf16c_kernel<1>,
                             cudaFuncAttributeMaxDynamicSharedMemorySize, GEMM_SMEM);
        cudaFuncSetAttribute(flash_mma_kernel,
                             cudaFuncAttributeMaxDynamicSharedMemorySize, FLASH_SMEM);
        attr_done = true;
    }

    const int ACT4 = MTOT*DIM/4, W4 = DIM*DIM/4;
    const dim3 gg(DIM/128, MTOT/128);   // (8, 64)

    // Q projection
    split_kernel<<<ACT4/256, 256>>>(q,  xh, xl, ACT4);
    split_kernel<<<W4/256,  256>>>(wq, wh, wl, W4);
    gemm_bf16c_kernel<1><<<gg, 256, GEMM_SMEM>>>(xh, xl, wh, wl, nullptr, qh, ql, MTOT, DIM, DIM);
    // K projection
    split_kernel<<<ACT4/256, 256>>>(k,  xh, xl, ACT4);
    split_kernel<<<W4/256,  256>>>(wk, wh, wl, W4);
    gemm_bf16c_kernel<1><<<gg, 256, GEMM_SMEM>>>(xh, xl, wh, wl, nullptr, kh, kl, MTOT, DIM, DIM);
    // V projection
    split_kernel<<<ACT4/256, 256>>>(v,  xh, xl, ACT4);
    split_kernel<<<W4/256,  256>>>(wv, wh, wl, W4);
    gemm_bf16c_kernel<1><<<gg, 256, GEMM_SMEM>>>(xh, xl, wh, wl, nullptr, vh, vl, MTOT, DIM, DIM);

    // Attention (tensor-core flash)
    flash_mma_kernel<<<dim3(SEQ/64, BATCH*NH), 128, FLASH_SMEM>>>(
        qh, ql, kh, kl, vh, vl, oh, ol);

    // Output projection
    split_kernel<<<W4/256, 256>>>(wo, wh, wl, W4);
    gemm_bf16c_kernel<0><<<gg, 256, GEMM_SMEM>>>(oh, ol, wh, wl, out, nullptr, nullptr, MTOT, DIM, DIM);
}